// round 1
// baseline (speedup 1.0000x reference)
#include <cuda_runtime.h>
#include <math.h>

#define NN 100000
#define EE 1600000
#define GG 256
#define NCLS 10
#define F6 768
#define SCAP 192
#define NEG 0.2f

static inline int cdiv(int a, int b) { return (a + b - 1) / b; }

// ---------------- device scratch (no allocations allowed) ----------------
__device__ int   g_cnt[NN];
__device__ int   g_start[NN + 1];
__device__ int   g_cursor[NN];
__device__ int   g_col[EE];
__device__ float g_p[EE];
__device__ float g_s1[3 * NN];
__device__ float g_s2[3 * NN];
__device__ float g_deg[NN];
__device__ float g_dinv[NN];
__device__ __align__(16) float g_bufA[NN * 128];
__device__ __align__(16) float g_bufB[NN * 128];
__device__ float g_feats[GG * F6];
__device__ float g_mlp1[GG * 256];
__device__ float g_mlp2[GG * 128];
__device__ int   g_cntg[GG];

// ---------------- utility kernels ----------------
__global__ void zero_f(float* p, int n) {
    int i = blockIdx.x * blockDim.x + threadIdx.x;
    if (i < n) p[i] = 0.f;
}
__global__ void zero_i(int* p, int n) {
    int i = blockIdx.x * blockDim.x + threadIdx.x;
    if (i < n) p[i] = 0;
}

// ---------------- CSR build (group edges by source row) ----------------
__global__ void hist_row(const int* __restrict__ row) {
    int e = blockIdx.x * blockDim.x + threadIdx.x;
    if (e < EE) atomicAdd(&g_cnt[row[e]], 1);
}

__global__ void scan_k() {
    __shared__ int sh[1024];
    __shared__ int carry;
    int tid = threadIdx.x;
    if (tid == 0) carry = 0;
    __syncthreads();
    int nch = (NN + 1023) / 1024;
    for (int c = 0; c < nch; c++) {
        int i = c * 1024 + tid;
        int v = (i < NN) ? g_cnt[i] : 0;
        sh[tid] = v;
        __syncthreads();
        for (int off = 1; off < 1024; off <<= 1) {
            int t = (tid >= off) ? sh[tid - off] : 0;
            __syncthreads();
            sh[tid] += t;
            __syncthreads();
        }
        int incl = sh[tid];
        int base = carry;
        if (i < NN) {
            int excl = base + incl - v;
            g_start[i] = excl;
            g_cursor[i] = excl;
        }
        __syncthreads();
        if (tid == 1023) carry = base + incl;
        __syncthreads();
    }
    if (tid == 0) g_start[NN] = carry;
}

__global__ void scatter_e(const int* __restrict__ row, const int* __restrict__ col) {
    int e = blockIdx.x * blockDim.x + threadIdx.x;
    if (e >= EE) return;
    int r = row[e];
    int pos = atomicAdd(&g_cursor[r], 1);
    g_col[pos] = col[e];
}

// ---------------- per-node attention scores (all 3 blocks at once) ----------------
__global__ void s12_k(const float* __restrict__ x, const float* __restrict__ att) {
    int t = blockIdx.x * blockDim.x + threadIdx.x;
    int u = t >> 5, lane = t & 31;
    if (u >= NN) return;
    float4 xv = *(const float4*)&x[u * 128 + lane * 4];
#pragma unroll
    for (int b = 0; b < 3; b++) {
        float4 a1 = *(const float4*)&att[b * 256 + lane * 4];
        float4 a2 = *(const float4*)&att[b * 256 + 128 + lane * 4];
        float d1 = xv.x * a1.x + xv.y * a1.y + xv.z * a1.z + xv.w * a1.w;
        float d2 = xv.x * a2.x + xv.y * a2.y + xv.z * a2.z + xv.w * a2.w;
#pragma unroll
        for (int o = 16; o > 0; o >>= 1) {
            d1 += __shfl_xor_sync(0xffffffffu, d1, o);
            d2 += __shfl_xor_sync(0xffffffffu, d2, o);
        }
        if (lane == 0) {
            g_s1[b * NN + u] = d1;
            g_s2[b * NN + u] = d2;
        }
    }
}

__device__ __forceinline__ float lrelu(float w) { return w >= 0.f ? w : NEG * w; }

// ---------------- exact segment sparsemax (warp per source node) ----------------
__global__ void sparsemax_k(int b) {
    __shared__ float sh[8][SCAP];
    int lane = threadIdx.x & 31, wl = threadIdx.x >> 5;
    int u = blockIdx.x * 8 + wl;
    if (u >= NN) return;
    int st = g_start[u], en = g_start[u + 1];
    int d = en - st;
    if (d == 0) return;
    float su = g_s1[b * NN + u];
    const float* s2b = &g_s2[b * NN];
    float* shz = sh[wl];
    for (int i = lane; i < d; i += 32) {
        float w = lrelu(su + s2b[g_col[st + i]]);
        if (i < SCAP) shz[i] = w;
    }
    __syncwarp();
    float kloc = 0.f, sloc = 0.f;
    for (int i = lane; i < d; i += 32) {
        float zi = (i < SCAP) ? shz[i] : lrelu(su + s2b[g_col[st + i]]);
        float rank = 1.f, S = zi;
        for (int j = 0; j < d; j++) {
            float zj = (j < SCAP) ? shz[j] : lrelu(su + s2b[g_col[st + j]]);
            if (zj > zi || (zj == zi && j < i)) { rank += 1.f; S += zj; }
        }
        if (1.f + rank * zi > S) { kloc += 1.f; sloc += zi; }
    }
#pragma unroll
    for (int o = 16; o > 0; o >>= 1) {
        kloc += __shfl_xor_sync(0xffffffffu, kloc, o);
        sloc += __shfl_xor_sync(0xffffffffu, sloc, o);
    }
    float tau = (sloc - 1.f) / kloc;  // k >= 1 always (top element satisfies cond)
    for (int i = lane; i < d; i += 32) {
        float zi = (i < SCAP) ? shz[i] : lrelu(su + s2b[g_col[st + i]]);
        float pv = fmaxf(zi - tau, 0.f);
        g_p[st + i] = pv;
        if (pv > 0.f) atomicAdd(&g_deg[g_col[st + i]], pv);
    }
}

__global__ void dinv_k() {
    int i = blockIdx.x * blockDim.x + threadIdx.x;
    if (i < NN) g_dinv[i] = rsqrtf(g_deg[i] + 1.0f);
}

// ---------------- fp32 SGEMM: [NN,128] x [128,128], optional relu on input ----------------
__global__ __launch_bounds__(256) void gemm_k(const float* __restrict__ A,
                                              const float* __restrict__ W,
                                              float* __restrict__ O, int relu_in) {
    __shared__ float As[32][68];   // [k][m], padded for conflict-free stores
    __shared__ float Ws[32][128];  // [k][n]
    int tid = threadIdx.x;
    int tx = tid & 15, ty = tid >> 4;
    int m0 = blockIdx.x * 64;
    float acc[4][8];
#pragma unroll
    for (int i = 0; i < 4; i++)
#pragma unroll
        for (int j = 0; j < 8; j++) acc[i][j] = 0.f;

    for (int k0 = 0; k0 < 128; k0 += 32) {
#pragma unroll
        for (int l = 0; l < 2; l++) {
            int idx = tid + l * 256;         // 0..511
            int r = idx >> 3, kg = idx & 7;  // 64 rows x 8 float4
            int gm = m0 + r;
            float4 v = make_float4(0.f, 0.f, 0.f, 0.f);
            if (gm < NN) v = *(const float4*)&A[gm * 128 + k0 + kg * 4];
            if (relu_in) {
                v.x = fmaxf(v.x, 0.f); v.y = fmaxf(v.y, 0.f);
                v.z = fmaxf(v.z, 0.f); v.w = fmaxf(v.w, 0.f);
            }
            As[kg * 4 + 0][r] = v.x; As[kg * 4 + 1][r] = v.y;
            As[kg * 4 + 2][r] = v.z; As[kg * 4 + 3][r] = v.w;
        }
#pragma unroll
        for (int l = 0; l < 4; l++) {
            int idx = tid + l * 256;           // 0..1023
            int kk = idx >> 5, n4 = idx & 31;  // 32 k x 32 float4
            *(float4*)&Ws[kk][n4 * 4] = *(const float4*)&W[(k0 + kk) * 128 + n4 * 4];
        }
        __syncthreads();
#pragma unroll
        for (int kk = 0; kk < 32; kk++) {
            float4 a = *(const float4*)&As[kk][ty * 4];
            float4 b0 = *(const float4*)&Ws[kk][tx * 8];
            float4 b1 = *(const float4*)&Ws[kk][tx * 8 + 4];
            float av[4] = {a.x, a.y, a.z, a.w};
            float bv[8] = {b0.x, b0.y, b0.z, b0.w, b1.x, b1.y, b1.z, b1.w};
#pragma unroll
            for (int i2 = 0; i2 < 4; i2++)
#pragma unroll
                for (int j2 = 0; j2 < 8; j2++) acc[i2][j2] += av[i2] * bv[j2];
        }
        __syncthreads();
    }
#pragma unroll
    for (int i2 = 0; i2 < 4; i2++) {
        int gm = m0 + ty * 4 + i2;
        if (gm < NN) {
            float4 o0 = make_float4(acc[i2][0], acc[i2][1], acc[i2][2], acc[i2][3]);
            float4 o1 = make_float4(acc[i2][4], acc[i2][5], acc[i2][6], acc[i2][7]);
            *(float4*)&O[gm * 128 + tx * 8] = o0;
            *(float4*)&O[gm * 128 + tx * 8 + 4] = o1;
        }
    }
}

// ---------------- GCN: init out = bias + h*dinv^2 (self loop) ----------------
__global__ void init_out_k(const float* __restrict__ h, const float* __restrict__ bias,
                           float* __restrict__ out) {
    int idx = blockIdx.x * blockDim.x + threadIdx.x;
    if (idx >= NN * 32) return;
    int v = idx >> 5, q = idx & 31;
    float dv = g_dinv[v];
    float d2 = dv * dv;
    float4 hv = *(const float4*)&h[v * 128 + q * 4];
    float4 bv = *(const float4*)&bias[q * 4];
    float4 o = make_float4(bv.x + hv.x * d2, bv.y + hv.y * d2,
                           bv.z + hv.z * d2, bv.w + hv.w * d2);
    *(float4*)&out[v * 128 + q * 4] = o;
}

// ---------------- GCN: edge scatter, warp per source (h[u] loaded once) ----------------
__global__ void scatter_conv_k(const float* __restrict__ h, float* __restrict__ out) {
    int t = blockIdx.x * blockDim.x + threadIdx.x;
    int u = t >> 5, lane = t & 31;
    if (u >= NN) return;
    int st = g_start[u], d = g_start[u + 1] - st;
    if (d == 0) return;
    float du = g_dinv[u];
    float4 hv = *(const float4*)&h[u * 128 + lane * 4];
    for (int j0 = 0; j0 < d; j0 += 32) {
        int i = j0 + lane;
        int c = 0; float pv = 0.f;
        if (i < d) { c = g_col[st + i]; pv = g_p[st + i]; }
        int lim = min(32, d - j0);
        for (int j = 0; j < lim; j++) {
            float pj = __shfl_sync(0xffffffffu, pv, j);
            int cj = __shfl_sync(0xffffffffu, c, j);
            if (pj == 0.f) continue;  // pruned edge: skip atomics entirely
            float norm = du * pj * g_dinv[cj];
            float* dst = &out[cj * 128 + lane * 4];
            atomicAdd(dst + 0, hv.x * norm);
            atomicAdd(dst + 1, hv.y * norm);
            atomicAdd(dst + 2, hv.z * norm);
            atomicAdd(dst + 3, hv.w * norm);
        }
    }
}

// ---------------- pooling (batch is sorted -> run-length local reduce) ----------------
__global__ void hist_batch_k(const int* __restrict__ batch) {
    int i = blockIdx.x * blockDim.x + threadIdx.x;
    if (i < NN) atomicAdd(&g_cntg[batch[i]], 1);
}

__global__ void pool_k(const float* __restrict__ z, const int* __restrict__ batch, int boff) {
    int f = threadIdx.x;  // 128 threads = one feature each
    int n0 = blockIdx.x * 256;
    if (n0 >= NN) return;
    int nend = min(n0 + 256, NN);
    int cur = batch[n0];
    float ls = 0.f, lm = 0.f;
    for (int n = n0; n < nend; n++) {
        int g = batch[n];
        if (g != cur) {
            atomicAdd(&g_feats[cur * F6 + boff + f], ls);
            atomicMax((int*)&g_feats[cur * F6 + boff + 128 + f], __float_as_int(lm));
            ls = 0.f; lm = 0.f; cur = g;
        }
        float v = fmaxf(z[n * 128 + f], 0.f);  // z = relu(conv2 out) >= 0
        ls += v;
        lm = fmaxf(lm, v);
    }
    atomicAdd(&g_feats[cur * F6 + boff + f], ls);
    atomicMax((int*)&g_feats[cur * F6 + boff + 128 + f], __float_as_int(lm));
}

__global__ void finalize_mean_k() {
    int i = blockIdx.x * blockDim.x + threadIdx.x;
    if (i >= GG * 384) return;
    int g = i / 384, r = i % 384;
    int b = r >> 7, f = r & 127;
    float c = (float)max(g_cntg[g], 1);
    g_feats[g * F6 + b * 256 + f] /= c;
}

// ---------------- tiny MLP head ----------------
__global__ void mlp1_k(const float* __restrict__ w, const float* __restrict__ bias) {
    __shared__ float sh[F6];
    int g = blockIdx.x, j = threadIdx.x;  // 256 threads
    for (int i = j; i < F6; i += 256) sh[i] = g_feats[g * F6 + i];
    __syncthreads();
    float acc = bias[j];
#pragma unroll 8
    for (int i = 0; i < F6; i++) acc += sh[i] * w[i * 256 + j];
    g_mlp1[g * 256 + j] = fmaxf(acc, 0.f);
}

__global__ void mlp2_k(const float* __restrict__ w, const float* __restrict__ bias) {
    __shared__ float sh[256];
    int g = blockIdx.x, j = threadIdx.x;  // 128 threads
    for (int i = j; i < 256; i += 128) sh[i] = g_mlp1[g * 256 + i];
    __syncthreads();
    float acc = bias[j];
#pragma unroll 8
    for (int i = 0; i < 256; i++) acc += sh[i] * w[i * 128 + j];
    g_mlp2[g * 128 + j] = fmaxf(acc, 0.f);
}

__global__ void mlp3_k(const float* __restrict__ w, const float* __restrict__ bias,
                       float* __restrict__ out) {
    int g = blockIdx.x, lane = threadIdx.x;  // 32 threads
    __shared__ float sh[128];
    for (int i = lane; i < 128; i += 32) sh[i] = g_mlp2[g * 128 + i];
    __syncwarp();
    float acc[NCLS];
#pragma unroll
    for (int c = 0; c < NCLS; c++) acc[c] = 0.f;
    for (int i = lane; i < 128; i += 32) {
        float v = sh[i];
#pragma unroll
        for (int c = 0; c < NCLS; c++) acc[c] += v * w[i * NCLS + c];
    }
#pragma unroll
    for (int c = 0; c < NCLS; c++)
#pragma unroll
        for (int o = 16; o > 0; o >>= 1) acc[c] += __shfl_xor_sync(0xffffffffu, acc[c], o);
    if (lane == 0) {
        float vals[NCLS], m = -1e30f;
        for (int c = 0; c < NCLS; c++) { vals[c] = acc[c] + bias[c]; m = fmaxf(m, vals[c]); }
        float s = 0.f;
        for (int c = 0; c < NCLS; c++) s += expf(vals[c] - m);
        float lse = logf(s);
        for (int c = 0; c < NCLS; c++) out[g * NCLS + c] = vals[c] - m - lse;
    }
}

// ---------------- host launch ----------------
extern "C" void kernel_launch(void* const* d_in, const int* in_sizes, int n_in,
                              void* d_out, int out_size) {
    const float* x = (const float*)d_in[0];
    const int* ei = (const int*)d_in[1];
    // d_in[2] = edge_attr: unused by the reference
    const int* batch = (const int*)d_in[3];
    int pi = (n_in >= 16) ? 5 : 4;  // num_graphs scalar may or may not be materialized
    const float* att  = (const float*)d_in[pi + 0];
    const float* W1   = (const float*)d_in[pi + 1];
    const float* b1   = (const float*)d_in[pi + 2];
    const float* W2   = (const float*)d_in[pi + 3];
    const float* b2   = (const float*)d_in[pi + 4];
    const float* fc1w = (const float*)d_in[pi + 5];
    const float* fc1b = (const float*)d_in[pi + 6];
    const float* fc2w = (const float*)d_in[pi + 7];
    const float* fc2b = (const float*)d_in[pi + 8];
    const float* fc3w = (const float*)d_in[pi + 9];
    const float* fc3b = (const float*)d_in[pi + 10];
    float* out = (float*)d_out;

    float *bufA, *bufB, *feats, *deg;
    int *cnt, *cntg;
    cudaGetSymbolAddress((void**)&bufA, g_bufA);
    cudaGetSymbolAddress((void**)&bufB, g_bufB);
    cudaGetSymbolAddress((void**)&feats, g_feats);
    cudaGetSymbolAddress((void**)&deg, g_deg);
    cudaGetSymbolAddress((void**)&cnt, g_cnt);
    cudaGetSymbolAddress((void**)&cntg, g_cntg);

    const int* row = ei;
    const int* col = ei + EE;

    // CSR by source row (reused by all 3 blocks)
    zero_i<<<cdiv(NN, 256), 256>>>(cnt, NN);
    hist_row<<<cdiv(EE, 256), 256>>>(row);
    scan_k<<<1, 1024>>>();
    scatter_e<<<cdiv(EE, 256), 256>>>(row, col);

    // attention scores for all blocks
    s12_k<<<cdiv(NN * 32, 256), 256>>>(x, att);

    // per-graph node counts + clear pooled features
    zero_i<<<1, 256>>>(cntg, GG);
    hist_batch_k<<<cdiv(NN, 256), 256>>>(batch);
    zero_f<<<cdiv(GG * F6, 256), 256>>>(feats, GG * F6);

    for (int b = 0; b < 3; b++) {
        zero_f<<<cdiv(NN, 256), 256>>>(deg, NN);
        sparsemax_k<<<cdiv(NN, 8), 256>>>(b);
        dinv_k<<<cdiv(NN, 256), 256>>>();

        // conv1: h = x @ W1; out = b1 + h*dinv^2 + scatter(norm*h[row] -> col)
        gemm_k<<<cdiv(NN, 64), 256>>>(x, W1 + b * 128 * 128, bufA, 0);
        init_out_k<<<cdiv(NN * 32, 256), 256>>>(bufA, b1 + b * 128, bufB);
        scatter_conv_k<<<cdiv(NN * 32, 256), 256>>>(bufA, bufB);

        // conv2: h = relu(conv1) @ W2 (relu fused into GEMM load)
        gemm_k<<<cdiv(NN, 64), 256>>>(bufB, W2 + b * 128 * 128, bufA, 1);
        init_out_k<<<cdiv(NN * 32, 256), 256>>>(bufA, b2 + b * 128, bufB);
        scatter_conv_k<<<cdiv(NN * 32, 256), 256>>>(bufA, bufB);

        // pool relu(conv2) into feats[g][b*256 .. b*256+255]
        pool_k<<<cdiv(NN, 256), 128>>>(bufB, batch, b * 256);
    }

    finalize_mean_k<<<cdiv(GG * 384, 256), 256>>>();
    mlp1_k<<<GG, 256>>>(fc1w, fc1b);
    mlp2_k<<<GG, 128>>>(fc2w, fc2b);
    mlp3_k<<<GG, 32>>>(fc3w, fc3b, out);

    (void)in_sizes;
    (void)out_size;
}

// round 2
// speedup vs baseline: 1.0445x; 1.0445x over previous
#include <cuda_runtime.h>
#include <math.h>

#define NN 100000
#define EE 1600000
#define GG 256
#define NCLS 10
#define F6 768
#define SCAP 192
#define NEG 0.2f

static inline int cdiv(int a, int b) { return (a + b - 1) / b; }

// ---------------- device scratch (no allocations allowed) ----------------
__device__ int   g_cntR[NN];
__device__ int   g_cntC[NN];
__device__ int   g_startR[NN + 1];
__device__ int   g_startC[NN + 1];
__device__ int   g_curR[NN];
__device__ int   g_curC[NN];
__device__ int   g_col[EE];    // CSR (by source): dest of each slot
__device__ int   g_crow[EE];   // CSC (by dest): source of each slot
__device__ int   g_cpidx[EE];  // CSC slot -> CSR slot (index into g_p)
__device__ float g_p[EE];      // sparsemax weights, CSR order
__device__ float g_ec[EE];     // per-edge coeff dinv[u]*p, CSC order
__device__ float g_s1[3 * NN];
__device__ float g_s2[3 * NN];
__device__ float g_dinv[NN];
__device__ __align__(16) float g_bufA[NN * 128];
__device__ __align__(16) float g_bufB[NN * 128];
__device__ float g_feats[GG * F6];
__device__ float g_mlp1[GG * 256];
__device__ float g_mlp2[GG * 128];
__device__ int   g_cntg[GG];

// ---------------- utility kernels ----------------
__global__ void zero_f(float* p, int n) {
    int i = blockIdx.x * blockDim.x + threadIdx.x;
    if (i < n) p[i] = 0.f;
}
__global__ void zero_i2(int* a, int* b, int n) {
    int i = blockIdx.x * blockDim.x + threadIdx.x;
    if (i < n) { a[i] = 0; b[i] = 0; }
}
__global__ void zero_cntg_k() {
    int i = threadIdx.x;
    if (i < GG) g_cntg[i] = 0;
}

// ---------------- CSR + CSC build ----------------
__global__ void hist_e(const int* __restrict__ row, const int* __restrict__ col) {
    int e = blockIdx.x * blockDim.x + threadIdx.x;
    if (e >= EE) return;
    atomicAdd(&g_cntR[row[e]], 1);
    atomicAdd(&g_cntC[col[e]], 1);
}

__global__ void scan_k(const int* __restrict__ cnt, int* __restrict__ start,
                       int* __restrict__ cursor) {
    __shared__ int sh[1024];
    __shared__ int carry;
    int tid = threadIdx.x;
    if (tid == 0) carry = 0;
    __syncthreads();
    int nch = (NN + 1023) / 1024;
    for (int c = 0; c < nch; c++) {
        int i = c * 1024 + tid;
        int v = (i < NN) ? cnt[i] : 0;
        sh[tid] = v;
        __syncthreads();
        for (int off = 1; off < 1024; off <<= 1) {
            int t = (tid >= off) ? sh[tid - off] : 0;
            __syncthreads();
            sh[tid] += t;
            __syncthreads();
        }
        int incl = sh[tid];
        int base = carry;
        if (i < NN) {
            int excl = base + incl - v;
            start[i] = excl;
            cursor[i] = excl;
        }
        __syncthreads();
        if (tid == 1023) carry = base + incl;
        __syncthreads();
    }
    if (tid == 0) start[NN] = carry;
}

__global__ void scatter_e(const int* __restrict__ row, const int* __restrict__ col) {
    int e = blockIdx.x * blockDim.x + threadIdx.x;
    if (e >= EE) return;
    int r = row[e], c = col[e];
    int p1 = atomicAdd(&g_curR[r], 1);
    g_col[p1] = c;
    int p2 = atomicAdd(&g_curC[c], 1);
    g_crow[p2] = r;
    g_cpidx[p2] = p1;
}

// ---------------- per-node attention scores (all 3 blocks at once) ----------------
__global__ void s12_k(const float* __restrict__ x, const float* __restrict__ att) {
    int t = blockIdx.x * blockDim.x + threadIdx.x;
    int u = t >> 5, lane = t & 31;
    if (u >= NN) return;
    float4 xv = *(const float4*)&x[u * 128 + lane * 4];
#pragma unroll
    for (int b = 0; b < 3; b++) {
        float4 a1 = *(const float4*)&att[b * 256 + lane * 4];
        float4 a2 = *(const float4*)&att[b * 256 + 128 + lane * 4];
        float d1 = xv.x * a1.x + xv.y * a1.y + xv.z * a1.z + xv.w * a1.w;
        float d2 = xv.x * a2.x + xv.y * a2.y + xv.z * a2.z + xv.w * a2.w;
#pragma unroll
        for (int o = 16; o > 0; o >>= 1) {
            d1 += __shfl_xor_sync(0xffffffffu, d1, o);
            d2 += __shfl_xor_sync(0xffffffffu, d2, o);
        }
        if (lane == 0) {
            g_s1[b * NN + u] = d1;
            g_s2[b * NN + u] = d2;
        }
    }
}

__device__ __forceinline__ float lrelu(float w) { return w >= 0.f ? w : NEG * w; }

// ---------------- exact segment sparsemax (warp per source node) ----------------
__global__ void sparsemax_k(int b) {
    __shared__ float sh[8][SCAP];
    int lane = threadIdx.x & 31, wl = threadIdx.x >> 5;
    int u = blockIdx.x * 8 + wl;
    if (u >= NN) return;
    int st = g_startR[u], en = g_startR[u + 1];
    int d = en - st;
    if (d == 0) return;
    float su = g_s1[b * NN + u];
    const float* s2b = &g_s2[b * NN];
    float* shz = sh[wl];
    for (int i = lane; i < d; i += 32) {
        float w = lrelu(su + s2b[g_col[st + i]]);
        if (i < SCAP) shz[i] = w;
    }
    __syncwarp();
    float kloc = 0.f, sloc = 0.f;
    for (int i = lane; i < d; i += 32) {
        float zi = (i < SCAP) ? shz[i] : lrelu(su + s2b[g_col[st + i]]);
        float rank = 1.f, S = zi;
        for (int j = 0; j < d; j++) {
            float zj = (j < SCAP) ? shz[j] : lrelu(su + s2b[g_col[st + j]]);
            if (zj > zi || (zj == zi && j < i)) { rank += 1.f; S += zj; }
        }
        if (1.f + rank * zi > S) { kloc += 1.f; sloc += zi; }
    }
#pragma unroll
    for (int o = 16; o > 0; o >>= 1) {
        kloc += __shfl_xor_sync(0xffffffffu, kloc, o);
        sloc += __shfl_xor_sync(0xffffffffu, sloc, o);
    }
    float tau = (sloc - 1.f) / kloc;  // k >= 1 always
    for (int i = lane; i < d; i += 32) {
        float zi = (i < SCAP) ? shz[i] : lrelu(su + s2b[g_col[st + i]]);
        g_p[st + i] = fmaxf(zi - tau, 0.f);
    }
}

// ---------------- dinv from CSC (no atomics) ----------------
__global__ void dinv_k() {
    int t = blockIdx.x * blockDim.x + threadIdx.x;
    int v = t >> 5, lane = t & 31;
    if (v >= NN) return;
    int st = g_startC[v], d = g_startC[v + 1] - st;
    float s = 0.f;
    for (int i = lane; i < d; i += 32) s += g_p[g_cpidx[st + i]];
#pragma unroll
    for (int o = 16; o > 0; o >>= 1) s += __shfl_xor_sync(0xffffffffu, s, o);
    if (lane == 0) g_dinv[v] = rsqrtf(s + 1.0f);
}

// ---------------- per-edge coefficient (CSC order): dinv[src]*p ----------------
__global__ void ecoef_k() {
    int i = blockIdx.x * blockDim.x + threadIdx.x;
    if (i >= EE) return;
    g_ec[i] = g_dinv[g_crow[i]] * g_p[g_cpidx[i]];
}

// ---------------- fp32 SGEMM 128x128 tile, 8x8 micro-tile ----------------
__global__ __launch_bounds__(256) void gemm_k(const float* __restrict__ A,
                                              const float* __restrict__ W,
                                              float* __restrict__ O, int relu_in) {
    __shared__ float As[16][132];  // [k][m]
    __shared__ float Ws[16][128];  // [k][n]
    int tid = threadIdx.x;
    int tx = tid & 15, ty = tid >> 4;
    int m0 = blockIdx.x * 128;
    float acc[8][8];
#pragma unroll
    for (int i = 0; i < 8; i++)
#pragma unroll
        for (int j = 0; j < 8; j++) acc[i][j] = 0.f;

    int r = tid >> 1;
    int gm = m0 + r;
    for (int k0 = 0; k0 < 128; k0 += 16) {
#pragma unroll
        for (int l = 0; l < 2; l++) {
            int kg = (tid & 1) * 2 + l;  // float4 group within the 16-k slab
            float4 v = make_float4(0.f, 0.f, 0.f, 0.f);
            if (gm < NN) v = *(const float4*)&A[gm * 128 + k0 + kg * 4];
            if (relu_in) {
                v.x = fmaxf(v.x, 0.f); v.y = fmaxf(v.y, 0.f);
                v.z = fmaxf(v.z, 0.f); v.w = fmaxf(v.w, 0.f);
            }
            As[kg * 4 + 0][r] = v.x; As[kg * 4 + 1][r] = v.y;
            As[kg * 4 + 2][r] = v.z; As[kg * 4 + 3][r] = v.w;
        }
#pragma unroll
        for (int l = 0; l < 2; l++) {
            int idx = tid + l * 256;           // 0..511
            int kk = idx >> 5, n4 = idx & 31;  // 16 k x 32 float4
            *(float4*)&Ws[kk][n4 * 4] = *(const float4*)&W[(k0 + kk) * 128 + n4 * 4];
        }
        __syncthreads();
#pragma unroll
        for (int kk = 0; kk < 16; kk++) {
            float4 a0 = *(const float4*)&As[kk][ty * 8];
            float4 a1 = *(const float4*)&As[kk][ty * 8 + 4];
            float4 b0 = *(const float4*)&Ws[kk][tx * 8];
            float4 b1 = *(const float4*)&Ws[kk][tx * 8 + 4];
            float av[8] = {a0.x, a0.y, a0.z, a0.w, a1.x, a1.y, a1.z, a1.w};
            float bv[8] = {b0.x, b0.y, b0.z, b0.w, b1.x, b1.y, b1.z, b1.w};
#pragma unroll
            for (int i2 = 0; i2 < 8; i2++)
#pragma unroll
                for (int j2 = 0; j2 < 8; j2++) acc[i2][j2] += av[i2] * bv[j2];
        }
        __syncthreads();
    }
#pragma unroll
    for (int i2 = 0; i2 < 8; i2++) {
        int gmo = m0 + ty * 8 + i2;
        if (gmo < NN) {
            float4 o0 = make_float4(acc[i2][0], acc[i2][1], acc[i2][2], acc[i2][3]);
            float4 o1 = make_float4(acc[i2][4], acc[i2][5], acc[i2][6], acc[i2][7]);
            *(float4*)&O[gmo * 128 + tx * 8] = o0;
            *(float4*)&O[gmo * 128 + tx * 8 + 4] = o1;
        }
    }
}

// ---------------- GCN aggregation: gather by destination, fused bias+self ----------------
__global__ void gather_conv_k(const float* __restrict__ h, const float* __restrict__ bias,
                              float* __restrict__ out) {
    int t = blockIdx.x * blockDim.x + threadIdx.x;
    int v = t >> 5, lane = t & 31;
    if (v >= NN) return;
    int st = g_startC[v], d = g_startC[v + 1] - st;
    float4 acc = make_float4(0.f, 0.f, 0.f, 0.f);
    for (int j0 = 0; j0 < d; j0 += 32) {
        int i = j0 + lane;
        int u = 0; float c = 0.f;
        if (i < d) { u = g_crow[st + i]; c = g_ec[st + i]; }
        int lim = min(32, d - j0);
        for (int j = 0; j < lim; j++) {
            float cj = __shfl_sync(0xffffffffu, c, j);
            int uj = __shfl_sync(0xffffffffu, u, j);
            if (cj == 0.f) continue;  // pruned edge: no traffic at all
            float4 hv = *(const float4*)&h[uj * 128 + lane * 4];
            acc.x += cj * hv.x; acc.y += cj * hv.y;
            acc.z += cj * hv.z; acc.w += cj * hv.w;
        }
    }
    float dv = g_dinv[v];
    float4 hv = *(const float4*)&h[v * 128 + lane * 4];
    float4 bv = *(const float4*)&bias[lane * 4];
    float4 o = make_float4(bv.x + dv * (acc.x + dv * hv.x),
                           bv.y + dv * (acc.y + dv * hv.y),
                           bv.z + dv * (acc.z + dv * hv.z),
                           bv.w + dv * (acc.w + dv * hv.w));
    *(float4*)&out[v * 128 + lane * 4] = o;
}

// ---------------- pooling (batch sorted -> run-length local reduce) ----------------
__global__ void hist_batch_k(const int* __restrict__ batch) {
    int i = blockIdx.x * blockDim.x + threadIdx.x;
    if (i < NN) atomicAdd(&g_cntg[batch[i]], 1);
}

__global__ void pool_k(const float* __restrict__ z, const int* __restrict__ batch, int boff) {
    int f = threadIdx.x;  // 128 threads = one feature each
    int n0 = blockIdx.x * 256;
    if (n0 >= NN) return;
    int nend = min(n0 + 256, NN);
    int cur = batch[n0];
    float ls = 0.f, lm = 0.f;
    for (int n = n0; n < nend; n++) {
        int g = batch[n];
        if (g != cur) {
            atomicAdd(&g_feats[cur * F6 + boff + f], ls);
            atomicMax((int*)&g_feats[cur * F6 + boff + 128 + f], __float_as_int(lm));
            ls = 0.f; lm = 0.f; cur = g;
        }
        float v = fmaxf(z[n * 128 + f], 0.f);  // z = relu(conv2 out) >= 0
        ls += v;
        lm = fmaxf(lm, v);
    }
    atomicAdd(&g_feats[cur * F6 + boff + f], ls);
    atomicMax((int*)&g_feats[cur * F6 + boff + 128 + f], __float_as_int(lm));
}

__global__ void finalize_mean_k() {
    int i = blockIdx.x * blockDim.x + threadIdx.x;
    if (i >= GG * 384) return;
    int g = i / 384, r = i % 384;
    int b = r >> 7, f = r & 127;
    float c = (float)max(g_cntg[g], 1);
    g_feats[g * F6 + b * 256 + f] /= c;
}

// ---------------- tiny MLP head ----------------
__global__ void mlp1_k(const float* __restrict__ w, const float* __restrict__ bias) {
    __shared__ float sh[F6];
    int g = blockIdx.x, j = threadIdx.x;  // 256 threads
    for (int i = j; i < F6; i += 256) sh[i] = g_feats[g * F6 + i];
    __syncthreads();
    float acc = bias[j];
#pragma unroll 8
    for (int i = 0; i < F6; i++) acc += sh[i] * w[i * 256 + j];
    g_mlp1[g * 256 + j] = fmaxf(acc, 0.f);
}

__global__ void mlp2_k(const float* __restrict__ w, const float* __restrict__ bias) {
    __shared__ float sh[256];
    int g = blockIdx.x, j = threadIdx.x;  // 128 threads
    for (int i = j; i < 256; i += 128) sh[i] = g_mlp1[g * 256 + i];
    __syncthreads();
    float acc = bias[j];
#pragma unroll 8
    for (int i = 0; i < 256; i++) acc += sh[i] * w[i * 128 + j];
    g_mlp2[g * 128 + j] = fmaxf(acc, 0.f);
}

__global__ void mlp3_k(const float* __restrict__ w, const float* __restrict__ bias,
                       float* __restrict__ out) {
    int g = blockIdx.x, lane = threadIdx.x;  // 32 threads
    __shared__ float sh[128];
    for (int i = lane; i < 128; i += 32) sh[i] = g_mlp2[g * 128 + i];
    __syncwarp();
    float acc[NCLS];
#pragma unroll
    for (int c = 0; c < NCLS; c++) acc[c] = 0.f;
    for (int i = lane; i < 128; i += 32) {
        float v = sh[i];
#pragma unroll
        for (int c = 0; c < NCLS; c++) acc[c] += v * w[i * NCLS + c];
    }
#pragma unroll
    for (int c = 0; c < NCLS; c++)
#pragma unroll
        for (int o = 16; o > 0; o >>= 1) acc[c] += __shfl_xor_sync(0xffffffffu, acc[c], o);
    if (lane == 0) {
        float vals[NCLS], m = -1e30f;
        for (int c = 0; c < NCLS; c++) { vals[c] = acc[c] + bias[c]; m = fmaxf(m, vals[c]); }
        float s = 0.f;
        for (int c = 0; c < NCLS; c++) s += expf(vals[c] - m);
        float lse = logf(s);
        for (int c = 0; c < NCLS; c++) out[g * NCLS + c] = vals[c] - m - lse;
    }
}

// ---------------- host launch ----------------
extern "C" void kernel_launch(void* const* d_in, const int* in_sizes, int n_in,
                              void* d_out, int out_size) {
    const float* x = (const float*)d_in[0];
    const int* ei = (const int*)d_in[1];
    // d_in[2] = edge_attr: unused by the reference
    const int* batch = (const int*)d_in[3];
    int pi = (n_in >= 16) ? 5 : 4;
    const float* att  = (const float*)d_in[pi + 0];
    const float* W1   = (const float*)d_in[pi + 1];
    const float* b1   = (const float*)d_in[pi + 2];
    const float* W2   = (const float*)d_in[pi + 3];
    const float* b2   = (const float*)d_in[pi + 4];
    const float* fc1w = (const float*)d_in[pi + 5];
    const float* fc1b = (const float*)d_in[pi + 6];
    const float* fc2w = (const float*)d_in[pi + 7];
    const float* fc2b = (const float*)d_in[pi + 8];
    const float* fc3w = (const float*)d_in[pi + 9];
    const float* fc3b = (const float*)d_in[pi + 10];
    float* out = (float*)d_out;

    float *bufA, *bufB, *feats;
    int *cntR, *cntC, *startR, *startC, *curR, *curC;
    cudaGetSymbolAddress((void**)&bufA, g_bufA);
    cudaGetSymbolAddress((void**)&bufB, g_bufB);
    cudaGetSymbolAddress((void**)&feats, g_feats);
    cudaGetSymbolAddress((void**)&cntR, g_cntR);
    cudaGetSymbolAddress((void**)&cntC, g_cntC);
    cudaGetSymbolAddress((void**)&startR, g_startR);
    cudaGetSymbolAddress((void**)&startC, g_startC);
    cudaGetSymbolAddress((void**)&curR, g_curR);
    cudaGetSymbolAddress((void**)&curC, g_curC);

    const int* row = ei;
    const int* col = ei + EE;

    // CSR (by source) + CSC (by dest), built once, reused by all 3 blocks
    zero_i2<<<cdiv(NN, 256), 256>>>(cntR, cntC, NN);
    hist_e<<<cdiv(EE, 256), 256>>>(row, col);
    scan_k<<<1, 1024>>>(cntR, startR, curR);
    scan_k<<<1, 1024>>>(cntC, startC, curC);
    scatter_e<<<cdiv(EE, 256), 256>>>(row, col);

    // attention scores for all blocks
    s12_k<<<cdiv(NN * 32, 256), 256>>>(x, att);

    // per-graph node counts + clear pooled features
    zero_cntg_k<<<1, 256>>>();
    hist_batch_k<<<cdiv(NN, 256), 256>>>(batch);
    zero_f<<<cdiv(GG * F6, 256), 256>>>(feats, GG * F6);

    for (int b = 0; b < 3; b++) {
        sparsemax_k<<<cdiv(NN, 8), 256>>>(b);
        dinv_k<<<cdiv(NN * 32, 256), 256>>>();
        ecoef_k<<<cdiv(EE, 256), 256>>>();

        // conv1: h = x @ W1; out = b1 + dinv*(gather + dinv*h)
        gemm_k<<<cdiv(NN, 128), 256>>>(x, W1 + b * 128 * 128, bufA, 0);
        gather_conv_k<<<cdiv(NN * 32, 256), 256>>>(bufA, b1 + b * 128, bufB);

        // conv2: h = relu(conv1) @ W2 (relu fused into GEMM load)
        gemm_k<<<cdiv(NN, 128), 256>>>(bufB, W2 + b * 128 * 128, bufA, 1);
        gather_conv_k<<<cdiv(NN * 32, 256), 256>>>(bufA, b2 + b * 128, bufB);

        // pool relu(conv2) into feats[g][b*256 .. b*256+255]
        pool_k<<<cdiv(NN, 256), 128>>>(bufB, batch, b * 256);
    }

    finalize_mean_k<<<cdiv(GG * 384, 256), 256>>>();
    mlp1_k<<<GG, 256>>>(fc1w, fc1b);
    mlp2_k<<<GG, 128>>>(fc2w, fc2b);
    mlp3_k<<<GG, 32>>>(fc3w, fc3b, out);

    (void)in_sizes;
    (void)out_size;
}

// round 3
// speedup vs baseline: 1.2338x; 1.1813x over previous
#include <cuda_runtime.h>
#include <math.h>

#define NN 100000
#define EE 1600000
#define GG 256
#define NCLS 10
#define F6 768
#define SCAP 192
#define NEG 0.2f
#define NB 98  // cdiv(NN, 1024)

static inline int cdiv(int a, int b) { return (a + b - 1) / b; }

// ---------------- device scratch (no allocations allowed) ----------------
__device__ int   g_cntR[NN];
__device__ int   g_cntC[NN];
__device__ int   g_startR[NN + 1];
__device__ int   g_startC[NN + 1];
__device__ int   g_curR[NN];
__device__ int   g_curC[NN];
__device__ int   g_inclR[NN];
__device__ int   g_inclC[NN];
__device__ int   g_bsumR[NB];
__device__ int   g_bsumC[NB];
__device__ int   g_col[EE];    // CSR (by source): dest of each slot
__device__ int   g_crow[EE];   // CSC (by dest): source of each slot
__device__ int   g_cpidx[EE];  // CSC slot -> CSR slot (index into g_p)
__device__ float g_p[EE];      // sparsemax weights, CSR order
__device__ float g_ec[EE];     // per-edge coeff dinv[u]*p, CSC order
__device__ float g_s1[3 * NN];
__device__ float g_s2[3 * NN];
__device__ float g_dinv[NN];
__device__ __align__(16) float g_bufA[NN * 128];
__device__ __align__(16) float g_bufB[NN * 128];
__device__ float g_feats[GG * F6];
__device__ float g_mlp1[GG * 256];
__device__ float g_mlp2[GG * 128];
__device__ int   g_cntg[GG];

// ---------------- utility kernels ----------------
__global__ void zero_f(float* p, int n) {
    int i = blockIdx.x * blockDim.x + threadIdx.x;
    if (i < n) p[i] = 0.f;
}
__global__ void zero_i2(int* a, int* b, int n) {
    int i = blockIdx.x * blockDim.x + threadIdx.x;
    if (i < n) { a[i] = 0; b[i] = 0; }
}
__global__ void zero_cntg_k() {
    int i = threadIdx.x;
    if (i < GG) g_cntg[i] = 0;
}

// ---------------- CSR + CSC build ----------------
__global__ void hist_e(const int* __restrict__ row, const int* __restrict__ col) {
    int e = blockIdx.x * blockDim.x + threadIdx.x;
    if (e >= EE) return;
    atomicAdd(&g_cntR[row[e]], 1);
    atomicAdd(&g_cntC[col[e]], 1);
}

// ---- 3-phase multi-block exclusive scan (both arrays in one pass) ----
__device__ __forceinline__ void block_incl_scan(int* sh, int tid) {
#pragma unroll
    for (int off = 1; off < 1024; off <<= 1) {
        int t = (tid >= off) ? sh[tid - off] : 0;
        __syncthreads();
        sh[tid] += t;
        __syncthreads();
    }
}

__global__ void scan_local(const int* __restrict__ cntA, int* __restrict__ inclA,
                           int* __restrict__ bsumA, const int* __restrict__ cntB,
                           int* __restrict__ inclB, int* __restrict__ bsumB) {
    __shared__ int sh[1024];
    int tid = threadIdx.x;
    int i = blockIdx.x * 1024 + tid;
    // array A
    sh[tid] = (i < NN) ? cntA[i] : 0;
    __syncthreads();
    block_incl_scan(sh, tid);
    if (i < NN) inclA[i] = sh[tid];
    if (tid == 1023) bsumA[blockIdx.x] = sh[1023];
    __syncthreads();
    // array B
    sh[tid] = (i < NN) ? cntB[i] : 0;
    __syncthreads();
    block_incl_scan(sh, tid);
    if (i < NN) inclB[i] = sh[tid];
    if (tid == 1023) bsumB[blockIdx.x] = sh[1023];
}

__global__ void scan_bsum() {
    __shared__ int sh[128];
    int tid = threadIdx.x;  // 128 threads, one block
    // array R
    sh[tid] = (tid < NB) ? g_bsumR[tid] : 0;
    __syncthreads();
#pragma unroll
    for (int off = 1; off < 128; off <<= 1) {
        int t = (tid >= off) ? sh[tid - off] : 0;
        __syncthreads();
        sh[tid] += t;
        __syncthreads();
    }
    if (tid < NB) g_bsumR[tid] = sh[tid] - ((tid < NB) ? 0 : 0) - (tid < NB ? g_bsumR[tid] : 0) + 0;  // placeholder
    __syncthreads();
    // The line above is wrong-prone; compute exclusive directly below instead.
    // (We re-load originals: sh currently inclusive; exclusive = inclusive - original.)
    // To avoid relying on overwritten values, redo cleanly:
    __shared__ int orig[128];
    // --- R redo ---
    orig[tid] = 0;
    __syncthreads();
    __syncthreads();
}

// NOTE: scan_bsum above got tangled; use the clean version below.
__global__ void scan_bsum2(int* __restrict__ bsum) {
    __shared__ int sh[128];
    __shared__ int orig[128];
    int tid = threadIdx.x;  // single block, 128 threads
    int v = (tid < NB) ? bsum[tid] : 0;
    sh[tid] = v;
    orig[tid] = v;
    __syncthreads();
#pragma unroll
    for (int off = 1; off < 128; off <<= 1) {
        int t = (tid >= off) ? sh[tid - off] : 0;
        __syncthreads();
        sh[tid] += t;
        __syncthreads();
    }
    if (tid < NB) bsum[tid] = sh[tid] - orig[tid];  // exclusive prefix
}

__global__ void scan_final(const int* __restrict__ cntA, const int* __restrict__ inclA,
                           const int* __restrict__ bsumA, int* __restrict__ startA,
                           int* __restrict__ curA, const int* __restrict__ cntB,
                           const int* __restrict__ inclB, const int* __restrict__ bsumB,
                           int* __restrict__ startB, int* __restrict__ curB) {
    int i = blockIdx.x * 1024 + threadIdx.x;
    if (i >= NN) return;
    int blk = blockIdx.x;
    int eA = bsumA[blk] + inclA[i] - cntA[i];
    startA[i] = eA;
    curA[i] = eA;
    int eB = bsumB[blk] + inclB[i] - cntB[i];
    startB[i] = eB;
    curB[i] = eB;
    if (i == 0) { startA[NN] = EE; startB[NN] = EE; }
}

__global__ void scatter_e(const int* __restrict__ row, const int* __restrict__ col) {
    int e = blockIdx.x * blockDim.x + threadIdx.x;
    if (e >= EE) return;
    int r = row[e], c = col[e];
    int p1 = atomicAdd(&g_curR[r], 1);
    g_col[p1] = c;
    int p2 = atomicAdd(&g_curC[c], 1);
    g_crow[p2] = r;
    g_cpidx[p2] = p1;
}

// ---------------- per-node attention scores (all 3 blocks at once) ----------------
__global__ void s12_k(const float* __restrict__ x, const float* __restrict__ att) {
    int t = blockIdx.x * blockDim.x + threadIdx.x;
    int u = t >> 5, lane = t & 31;
    if (u >= NN) return;
    float4 xv = *(const float4*)&x[u * 128 + lane * 4];
#pragma unroll
    for (int b = 0; b < 3; b++) {
        float4 a1 = *(const float4*)&att[b * 256 + lane * 4];
        float4 a2 = *(const float4*)&att[b * 256 + 128 + lane * 4];
        float d1 = xv.x * a1.x + xv.y * a1.y + xv.z * a1.z + xv.w * a1.w;
        float d2 = xv.x * a2.x + xv.y * a2.y + xv.z * a2.z + xv.w * a2.w;
#pragma unroll
        for (int o = 16; o > 0; o >>= 1) {
            d1 += __shfl_xor_sync(0xffffffffu, d1, o);
            d2 += __shfl_xor_sync(0xffffffffu, d2, o);
        }
        if (lane == 0) {
            g_s1[b * NN + u] = d1;
            g_s2[b * NN + u] = d2;
        }
    }
}

__device__ __forceinline__ float lrelu(float w) { return w >= 0.f ? w : NEG * w; }

// ---------------- exact segment sparsemax (warp per source node) ----------------
__global__ void sparsemax_k(int b) {
    __shared__ float sh[8][SCAP];
    int lane = threadIdx.x & 31, wl = threadIdx.x >> 5;
    int u = blockIdx.x * 8 + wl;
    if (u >= NN) return;
    int st = g_startR[u], en = g_startR[u + 1];
    int d = en - st;
    if (d == 0) return;
    float su = g_s1[b * NN + u];
    const float* s2b = &g_s2[b * NN];
    float* shz = sh[wl];
    for (int i = lane; i < d; i += 32) {
        float w = lrelu(su + s2b[g_col[st + i]]);
        if (i < SCAP) shz[i] = w;
    }
    __syncwarp();
    float kloc = 0.f, sloc = 0.f;
    for (int i = lane; i < d; i += 32) {
        float zi = (i < SCAP) ? shz[i] : lrelu(su + s2b[g_col[st + i]]);
        float rank = 1.f, S = zi;
        for (int j = 0; j < d; j++) {
            float zj = (j < SCAP) ? shz[j] : lrelu(su + s2b[g_col[st + j]]);
            if (zj > zi || (zj == zi && j < i)) { rank += 1.f; S += zj; }
        }
        if (1.f + rank * zi > S) { kloc += 1.f; sloc += zi; }
    }
#pragma unroll
    for (int o = 16; o > 0; o >>= 1) {
        kloc += __shfl_xor_sync(0xffffffffu, kloc, o);
        sloc += __shfl_xor_sync(0xffffffffu, sloc, o);
    }
    float tau = (sloc - 1.f) / kloc;  // k >= 1 always
    for (int i = lane; i < d; i += 32) {
        float zi = (i < SCAP) ? shz[i] : lrelu(su + s2b[g_col[st + i]]);
        g_p[st + i] = fmaxf(zi - tau, 0.f);
    }
}

// ---------------- dinv from CSC (no atomics) ----------------
__global__ void dinv_k() {
    int t = blockIdx.x * blockDim.x + threadIdx.x;
    int v = t >> 5, lane = t & 31;
    if (v >= NN) return;
    int st = g_startC[v], d = g_startC[v + 1] - st;
    float s = 0.f;
    for (int i = lane; i < d; i += 32) s += g_p[g_cpidx[st + i]];
#pragma unroll
    for (int o = 16; o > 0; o >>= 1) s += __shfl_xor_sync(0xffffffffu, s, o);
    if (lane == 0) g_dinv[v] = rsqrtf(s + 1.0f);
}

// ---------------- per-edge coefficient (CSC order): dinv[src]*p ----------------
__global__ void ecoef_k() {
    int i = blockIdx.x * blockDim.x + threadIdx.x;
    if (i >= EE) return;
    g_ec[i] = g_dinv[g_crow[i]] * g_p[g_cpidx[i]];
}

// ---------------- fp32 SGEMM 128x128 tile, 8x8 micro-tile ----------------
__global__ __launch_bounds__(256) void gemm_k(const float* __restrict__ A,
                                              const float* __restrict__ W,
                                              float* __restrict__ O, int relu_in) {
    __shared__ float As[16][132];  // [k][m]
    __shared__ float Ws[16][128];  // [k][n]
    int tid = threadIdx.x;
    int tx = tid & 15, ty = tid >> 4;
    int m0 = blockIdx.x * 128;
    float acc[8][8];
#pragma unroll
    for (int i = 0; i < 8; i++)
#pragma unroll
        for (int j = 0; j < 8; j++) acc[i][j] = 0.f;

    int r = tid >> 1;
    int gm = m0 + r;
    for (int k0 = 0; k0 < 128; k0 += 16) {
#pragma unroll
        for (int l = 0; l < 2; l++) {
            int kg = (tid & 1) * 2 + l;  // float4 group within the 16-k slab
            float4 v = make_float4(0.f, 0.f, 0.f, 0.f);
            if (gm < NN) v = *(const float4*)&A[gm * 128 + k0 + kg * 4];
            if (relu_in) {
                v.x = fmaxf(v.x, 0.f); v.y = fmaxf(v.y, 0.f);
                v.z = fmaxf(v.z, 0.f); v.w = fmaxf(v.w, 0.f);
            }
            As[kg * 4 + 0][r] = v.x; As[kg * 4 + 1][r] = v.y;
            As[kg * 4 + 2][r] = v.z; As[kg * 4 + 3][r] = v.w;
        }
#pragma unroll
        for (int l = 0; l < 2; l++) {
            int idx = tid + l * 256;           // 0..511
            int kk = idx >> 5, n4 = idx & 31;  // 16 k x 32 float4
            *(float4*)&Ws[kk][n4 * 4] = *(const float4*)&W[(k0 + kk) * 128 + n4 * 4];
        }
        __syncthreads();
#pragma unroll
        for (int kk = 0; kk < 16; kk++) {
            float4 a0 = *(const float4*)&As[kk][ty * 8];
            float4 a1 = *(const float4*)&As[kk][ty * 8 + 4];
            float4 b0 = *(const float4*)&Ws[kk][tx * 8];
            float4 b1 = *(const float4*)&Ws[kk][tx * 8 + 4];
            float av[8] = {a0.x, a0.y, a0.z, a0.w, a1.x, a1.y, a1.z, a1.w};
            float bv[8] = {b0.x, b0.y, b0.z, b0.w, b1.x, b1.y, b1.z, b1.w};
#pragma unroll
            for (int i2 = 0; i2 < 8; i2++)
#pragma unroll
                for (int j2 = 0; j2 < 8; j2++) acc[i2][j2] += av[i2] * bv[j2];
        }
        __syncthreads();
    }
#pragma unroll
    for (int i2 = 0; i2 < 8; i2++) {
        int gmo = m0 + ty * 8 + i2;
        if (gmo < NN) {
            float4 o0 = make_float4(acc[i2][0], acc[i2][1], acc[i2][2], acc[i2][3]);
            float4 o1 = make_float4(acc[i2][4], acc[i2][5], acc[i2][6], acc[i2][7]);
            *(float4*)&O[gmo * 128 + tx * 8] = o0;
            *(float4*)&O[gmo * 128 + tx * 8 + 4] = o1;
        }
    }
}

// ---------------- GCN aggregation: gather by destination, fused bias+self ----------------
__global__ void gather_conv_k(const float* __restrict__ h, const float* __restrict__ bias,
                              float* __restrict__ out) {
    int t = blockIdx.x * blockDim.x + threadIdx.x;
    int v = t >> 5, lane = t & 31;
    if (v >= NN) return;
    int st = g_startC[v], d = g_startC[v + 1] - st;
    float4 acc = make_float4(0.f, 0.f, 0.f, 0.f);
    for (int j0 = 0; j0 < d; j0 += 32) {
        int i = j0 + lane;
        int u = 0; float c = 0.f;
        if (i < d) { u = g_crow[st + i]; c = g_ec[st + i]; }
        int lim = min(32, d - j0);
        for (int j = 0; j < lim; j++) {
            float cj = __shfl_sync(0xffffffffu, c, j);
            int uj = __shfl_sync(0xffffffffu, u, j);
            if (cj == 0.f) continue;  // pruned edge: no traffic at all
            float4 hv = *(const float4*)&h[uj * 128 + lane * 4];
            acc.x += cj * hv.x; acc.y += cj * hv.y;
            acc.z += cj * hv.z; acc.w += cj * hv.w;
        }
    }
    float dv = g_dinv[v];
    float4 hv = *(const float4*)&h[v * 128 + lane * 4];
    float4 bv = *(const float4*)&bias[lane * 4];
    float4 o = make_float4(bv.x + dv * (acc.x + dv * hv.x),
                           bv.y + dv * (acc.y + dv * hv.y),
                           bv.z + dv * (acc.z + dv * hv.z),
                           bv.w + dv * (acc.w + dv * hv.w));
    *(float4*)&out[v * 128 + lane * 4] = o;
}

// ---------------- pooling (batch sorted -> run-length local reduce) ----------------
__global__ void hist_batch_k(const int* __restrict__ batch) {
    int i = blockIdx.x * blockDim.x + threadIdx.x;
    if (i < NN) atomicAdd(&g_cntg[batch[i]], 1);
}

__global__ void pool_k(const float* __restrict__ z, const int* __restrict__ batch, int boff) {
    int f = threadIdx.x;  // 128 threads = one feature each
    int n0 = blockIdx.x * 256;
    if (n0 >= NN) return;
    int nend = min(n0 + 256, NN);
    int cur = batch[n0];
    float ls = 0.f, lm = 0.f;
    for (int n = n0; n < nend; n++) {
        int g = batch[n];
        if (g != cur) {
            atomicAdd(&g_feats[cur * F6 + boff + f], ls);
            atomicMax((int*)&g_feats[cur * F6 + boff + 128 + f], __float_as_int(lm));
            ls = 0.f; lm = 0.f; cur = g;
        }
        float v = fmaxf(z[n * 128 + f], 0.f);  // z = relu(conv2 out) >= 0
        ls += v;
        lm = fmaxf(lm, v);
    }
    atomicAdd(&g_feats[cur * F6 + boff + f], ls);
    atomicMax((int*)&g_feats[cur * F6 + boff + 128 + f], __float_as_int(lm));
}

__global__ void finalize_mean_k() {
    int i = blockIdx.x * blockDim.x + threadIdx.x;
    if (i >= GG * 384) return;
    int g = i / 384, r = i % 384;
    int b = r >> 7, f = r & 127;
    float c = (float)max(g_cntg[g], 1);
    g_feats[g * F6 + b * 256 + f] /= c;
}

// ---------------- tiny MLP head ----------------
__global__ void mlp1_k(const float* __restrict__ w, const float* __restrict__ bias) {
    __shared__ float sh[F6];
    int g = blockIdx.x, j = threadIdx.x;  // 256 threads
    for (int i = j; i < F6; i += 256) sh[i] = g_feats[g * F6 + i];
    __syncthreads();
    float acc = bias[j];
#pragma unroll 8
    for (int i = 0; i < F6; i++) acc += sh[i] * w[i * 256 + j];
    g_mlp1[g * 256 + j] = fmaxf(acc, 0.f);
}

__global__ void mlp2_k(const float* __restrict__ w, const float* __restrict__ bias) {
    __shared__ float sh[256];
    int g = blockIdx.x, j = threadIdx.x;  // 128 threads
    for (int i = j; i < 256; i += 128) sh[i] = g_mlp1[g * 256 + i];
    __syncthreads();
    float acc = bias[j];
#pragma unroll 8
    for (int i = 0; i < 256; i++) acc += sh[i] * w[i * 128 + j];
    g_mlp2[g * 128 + j] = fmaxf(acc, 0.f);
}

__global__ void mlp3_k(const float* __restrict__ w, const float* __restrict__ bias,
                       float* __restrict__ out) {
    int g = blockIdx.x, lane = threadIdx.x;  // 32 threads
    __shared__ float sh[128];
    for (int i = lane; i < 128; i += 32) sh[i] = g_mlp2[g * 128 + i];
    __syncwarp();
    float acc[NCLS];
#pragma unroll
    for (int c = 0; c < NCLS; c++) acc[c] = 0.f;
    for (int i = lane; i < 128; i += 32) {
        float v = sh[i];
#pragma unroll
        for (int c = 0; c < NCLS; c++) acc[c] += v * w[i * NCLS + c];
    }
#pragma unroll
    for (int c = 0; c < NCLS; c++)
#pragma unroll
        for (int o = 16; o > 0; o >>= 1) acc[c] += __shfl_xor_sync(0xffffffffu, acc[c], o);
    if (lane == 0) {
        float vals[NCLS], m = -1e30f;
        for (int c = 0; c < NCLS; c++) { vals[c] = acc[c] + bias[c]; m = fmaxf(m, vals[c]); }
        float s = 0.f;
        for (int c = 0; c < NCLS; c++) s += expf(vals[c] - m);
        float lse = logf(s);
        for (int c = 0; c < NCLS; c++) out[g * NCLS + c] = vals[c] - m - lse;
    }
}

// ---------------- host launch ----------------
extern "C" void kernel_launch(void* const* d_in, const int* in_sizes, int n_in,
                              void* d_out, int out_size) {
    const float* x = (const float*)d_in[0];
    const int* ei = (const int*)d_in[1];
    // d_in[2] = edge_attr: unused by the reference
    const int* batch = (const int*)d_in[3];
    int pi = (n_in >= 16) ? 5 : 4;
    const float* att  = (const float*)d_in[pi + 0];
    const float* W1   = (const float*)d_in[pi + 1];
    const float* b1   = (const float*)d_in[pi + 2];
    const float* W2   = (const float*)d_in[pi + 3];
    const float* b2   = (const float*)d_in[pi + 4];
    const float* fc1w = (const float*)d_in[pi + 5];
    const float* fc1b = (const float*)d_in[pi + 6];
    const float* fc2w = (const float*)d_in[pi + 7];
    const float* fc2b = (const float*)d_in[pi + 8];
    const float* fc3w = (const float*)d_in[pi + 9];
    const float* fc3b = (const float*)d_in[pi + 10];
    float* out = (float*)d_out;

    float *bufA, *bufB, *feats;
    int *cntR, *cntC, *startR, *startC, *curR, *curC;
    int *inclR, *inclC, *bsumR, *bsumC;
    cudaGetSymbolAddress((void**)&bufA, g_bufA);
    cudaGetSymbolAddress((void**)&bufB, g_bufB);
    cudaGetSymbolAddress((void**)&feats, g_feats);
    cudaGetSymbolAddress((void**)&cntR, g_cntR);
    cudaGetSymbolAddress((void**)&cntC, g_cntC);
    cudaGetSymbolAddress((void**)&startR, g_startR);
    cudaGetSymbolAddress((void**)&startC, g_startC);
    cudaGetSymbolAddress((void**)&curR, g_curR);
    cudaGetSymbolAddress((void**)&curC, g_curC);
    cudaGetSymbolAddress((void**)&inclR, g_inclR);
    cudaGetSymbolAddress((void**)&inclC, g_inclC);
    cudaGetSymbolAddress((void**)&bsumR, g_bsumR);
    cudaGetSymbolAddress((void**)&bsumC, g_bsumC);

    const int* row = ei;
    const int* col = ei + EE;

    // CSR (by source) + CSC (by dest), built once, reused by all 3 blocks
    zero_i2<<<cdiv(NN, 256), 256>>>(cntR, cntC, NN);
    hist_e<<<cdiv(EE, 256), 256>>>(row, col);
    scan_local<<<NB, 1024>>>(cntR, inclR, bsumR, cntC, inclC, bsumC);
    scan_bsum2<<<1, 128>>>(bsumR);
    scan_bsum2<<<1, 128>>>(bsumC);
    scan_final<<<NB, 1024>>>(cntR, inclR, bsumR, startR, curR,
                             cntC, inclC, bsumC, startC, curC);
    scatter_e<<<cdiv(EE, 256), 256>>>(row, col);

    // attention scores for all blocks
    s12_k<<<cdiv(NN * 32, 256), 256>>>(x, att);

    // per-graph node counts + clear pooled features
    zero_cntg_k<<<1, 256>>>();
    hist_batch_k<<<cdiv(NN, 256), 256>>>(batch);
    zero_f<<<cdiv(GG * F6, 256), 256>>>(feats, GG * F6);

    for (int b = 0; b < 3; b++) {
        sparsemax_k<<<cdiv(NN, 8), 256>>>(b);
        dinv_k<<<cdiv(NN * 32, 256), 256>>>();
        ecoef_k<<<cdiv(EE, 256), 256>>>();

        // conv1: h = x @ W1; out = b1 + dinv*(gather + dinv*h)
        gemm_k<<<cdiv(NN, 128), 256>>>(x, W1 + b * 128 * 128, bufA, 0);
        gather_conv_k<<<cdiv(NN * 32, 256), 256>>>(bufA, b1 + b * 128, bufB);

        // conv2: h = relu(conv1) @ W2 (relu fused into GEMM load)
        gemm_k<<<cdiv(NN, 128), 256>>>(bufB, W2 + b * 128 * 128, bufA, 1);
        gather_conv_k<<<cdiv(NN * 32, 256), 256>>>(bufA, b2 + b * 128, bufB);

        // pool relu(conv2) into feats[g][b*256 .. b*256+255]
        pool_k<<<cdiv(NN, 256), 128>>>(bufB, batch, b * 256);
    }

    finalize_mean_k<<<cdiv(GG * 384, 256), 256>>>();
    mlp1_k<<<GG, 256>>>(fc1w, fc1b);
    mlp2_k<<<GG, 128>>>(fc2w, fc2b);
    mlp3_k<<<GG, 32>>>(fc3w, fc3b, out);

    (void)in_sizes;
    (void)out_size;
}

// round 4
// speedup vs baseline: 1.3887x; 1.1255x over previous
#include <cuda_runtime.h>
#include <mma.h>
#include <math.h>

using namespace nvcuda;

#define NN 100000
#define EE 1600000
#define GG 256
#define NCLS 10
#define F6 768
#define SCAP 192
#define NEG 0.2f
#define NB 98  // cdiv(NN, 1024)

#define GEMM_SMEM_FLOATS (128 * 128 + 64 * 132)
#define GEMM_SMEM_BYTES (GEMM_SMEM_FLOATS * 4)

static inline int cdiv(int a, int b) { return (a + b - 1) / b; }

// ---------------- device scratch (no allocations allowed) ----------------
__device__ int   g_cntR[NN];
__device__ int   g_cntC[NN];
__device__ int   g_startR[NN + 1];
__device__ int   g_startC[NN + 1];
__device__ int   g_curR[NN];
__device__ int   g_curC[NN];
__device__ int   g_inclR[NN];
__device__ int   g_inclC[NN];
__device__ int   g_bsumR[NB];
__device__ int   g_bsumC[NB];
__device__ int   g_col[EE];    // CSR (by source): dest of each slot
__device__ int   g_crow[EE];   // CSC (by dest): source of each slot
__device__ int   g_cpidx[EE];  // CSC slot -> CSR slot (index into g_p)
__device__ float g_p[EE];      // sparsemax weights, CSR order
__device__ float g_ec[EE];     // per-edge coeff dinv[u]*p, CSC order
__device__ float g_s1[3 * NN];
__device__ float g_s2[3 * NN];
__device__ float g_dinv[NN];
__device__ __align__(16) float g_bufA[NN * 128];
__device__ __align__(16) float g_bufB[NN * 128];
__device__ float g_feats[GG * F6];
__device__ float g_mlp1[GG * 256];
__device__ float g_mlp2[GG * 128];
__device__ int   g_cntg[GG];

// ---------------- utility kernels ----------------
__global__ void zero_f(float* p, int n) {
    int i = blockIdx.x * blockDim.x + threadIdx.x;
    if (i < n) p[i] = 0.f;
}
__global__ void zero_i2(int* a, int* b, int n) {
    int i = blockIdx.x * blockDim.x + threadIdx.x;
    if (i < n) { a[i] = 0; b[i] = 0; }
}
__global__ void zero_cntg_k() {
    int i = threadIdx.x;
    if (i < GG) g_cntg[i] = 0;
}

// ---------------- CSR + CSC build ----------------
__global__ void hist_e(const int* __restrict__ row, const int* __restrict__ col) {
    int e = blockIdx.x * blockDim.x + threadIdx.x;
    if (e >= EE) return;
    atomicAdd(&g_cntR[row[e]], 1);
    atomicAdd(&g_cntC[col[e]], 1);
}

__device__ __forceinline__ void block_incl_scan(int* sh, int tid) {
#pragma unroll
    for (int off = 1; off < 1024; off <<= 1) {
        int t = (tid >= off) ? sh[tid - off] : 0;
        __syncthreads();
        sh[tid] += t;
        __syncthreads();
    }
}

__global__ void scan_local(const int* __restrict__ cntA, int* __restrict__ inclA,
                           int* __restrict__ bsumA, const int* __restrict__ cntB,
                           int* __restrict__ inclB, int* __restrict__ bsumB) {
    __shared__ int sh[1024];
    int tid = threadIdx.x;
    int i = blockIdx.x * 1024 + tid;
    sh[tid] = (i < NN) ? cntA[i] : 0;
    __syncthreads();
    block_incl_scan(sh, tid);
    if (i < NN) inclA[i] = sh[tid];
    if (tid == 1023) bsumA[blockIdx.x] = sh[1023];
    __syncthreads();
    sh[tid] = (i < NN) ? cntB[i] : 0;
    __syncthreads();
    block_incl_scan(sh, tid);
    if (i < NN) inclB[i] = sh[tid];
    if (tid == 1023) bsumB[blockIdx.x] = sh[1023];
}

__global__ void scan_bsum2(int* __restrict__ bsum) {
    __shared__ int sh[128];
    __shared__ int orig[128];
    int tid = threadIdx.x;  // single block, 128 threads
    int v = (tid < NB) ? bsum[tid] : 0;
    sh[tid] = v;
    orig[tid] = v;
    __syncthreads();
#pragma unroll
    for (int off = 1; off < 128; off <<= 1) {
        int t = (tid >= off) ? sh[tid - off] : 0;
        __syncthreads();
        sh[tid] += t;
        __syncthreads();
    }
    if (tid < NB) bsum[tid] = sh[tid] - orig[tid];  // exclusive prefix
}

__global__ void scan_final(const int* __restrict__ cntA, const int* __restrict__ inclA,
                           const int* __restrict__ bsumA, int* __restrict__ startA,
                           int* __restrict__ curA, const int* __restrict__ cntB,
                           const int* __restrict__ inclB, const int* __restrict__ bsumB,
                           int* __restrict__ startB, int* __restrict__ curB) {
    int i = blockIdx.x * 1024 + threadIdx.x;
    if (i >= NN) return;
    int blk = blockIdx.x;
    int eA = bsumA[blk] + inclA[i] - cntA[i];
    startA[i] = eA;
    curA[i] = eA;
    int eB = bsumB[blk] + inclB[i] - cntB[i];
    startB[i] = eB;
    curB[i] = eB;
    if (i == 0) { startA[NN] = EE; startB[NN] = EE; }
}

__global__ void scatter_e(const int* __restrict__ row, const int* __restrict__ col) {
    int e = blockIdx.x * blockDim.x + threadIdx.x;
    if (e >= EE) return;
    int r = row[e], c = col[e];
    int p1 = atomicAdd(&g_curR[r], 1);
    g_col[p1] = c;
    int p2 = atomicAdd(&g_curC[c], 1);
    g_crow[p2] = r;
    g_cpidx[p2] = p1;
}

// ---------------- per-node attention scores (all 3 blocks at once) ----------------
__global__ void s12_k(const float* __restrict__ x, const float* __restrict__ att) {
    int t = blockIdx.x * blockDim.x + threadIdx.x;
    int u = t >> 5, lane = t & 31;
    if (u >= NN) return;
    float4 xv = *(const float4*)&x[u * 128 + lane * 4];
#pragma unroll
    for (int b = 0; b < 3; b++) {
        float4 a1 = *(const float4*)&att[b * 256 + lane * 4];
        float4 a2 = *(const float4*)&att[b * 256 + 128 + lane * 4];
        float d1 = xv.x * a1.x + xv.y * a1.y + xv.z * a1.z + xv.w * a1.w;
        float d2 = xv.x * a2.x + xv.y * a2.y + xv.z * a2.z + xv.w * a2.w;
#pragma unroll
        for (int o = 16; o > 0; o >>= 1) {
            d1 += __shfl_xor_sync(0xffffffffu, d1, o);
            d2 += __shfl_xor_sync(0xffffffffu, d2, o);
        }
        if (lane == 0) {
            g_s1[b * NN + u] = d1;
            g_s2[b * NN + u] = d2;
        }
    }
}

__device__ __forceinline__ float lrelu(float w) { return w >= 0.f ? w : NEG * w; }

// ---------------- exact segment sparsemax (warp per source node) ----------------
__global__ void sparsemax_k(int b) {
    __shared__ float sh[8][SCAP];
    int lane = threadIdx.x & 31, wl = threadIdx.x >> 5;
    int u = blockIdx.x * 8 + wl;
    if (u >= NN) return;
    int st = g_startR[u], en = g_startR[u + 1];
    int d = en - st;
    if (d == 0) return;
    float su = g_s1[b * NN + u];
    const float* s2b = &g_s2[b * NN];
    float* shz = sh[wl];
    for (int i = lane; i < d; i += 32) {
        float w = lrelu(su + s2b[g_col[st + i]]);
        if (i < SCAP) shz[i] = w;
    }
    __syncwarp();
    float kloc = 0.f, sloc = 0.f;
    for (int i = lane; i < d; i += 32) {
        float zi = (i < SCAP) ? shz[i] : lrelu(su + s2b[g_col[st + i]]);
        float rank = 1.f, S = zi;
        for (int j = 0; j < d; j++) {
            float zj = (j < SCAP) ? shz[j] : lrelu(su + s2b[g_col[st + j]]);
            if (zj > zi || (zj == zi && j < i)) { rank += 1.f; S += zj; }
        }
        if (1.f + rank * zi > S) { kloc += 1.f; sloc += zi; }
    }
#pragma unroll
    for (int o = 16; o > 0; o >>= 1) {
        kloc += __shfl_xor_sync(0xffffffffu, kloc, o);
        sloc += __shfl_xor_sync(0xffffffffu, sloc, o);
    }
    float tau = (sloc - 1.f) / kloc;  // k >= 1 always
    for (int i = lane; i < d; i += 32) {
        float zi = (i < SCAP) ? shz[i] : lrelu(su + s2b[g_col[st + i]]);
        g_p[st + i] = fmaxf(zi - tau, 0.f);
    }
}

// ---------------- dinv from CSC (no atomics) ----------------
__global__ void dinv_k() {
    int t = blockIdx.x * blockDim.x + threadIdx.x;
    int v = t >> 5, lane = t & 31;
    if (v >= NN) return;
    int st = g_startC[v], d = g_startC[v + 1] - st;
    float s = 0.f;
    for (int i = lane; i < d; i += 32) s += g_p[g_cpidx[st + i]];
#pragma unroll
    for (int o = 16; o > 0; o >>= 1) s += __shfl_xor_sync(0xffffffffu, s, o);
    if (lane == 0) g_dinv[v] = rsqrtf(s + 1.0f);
}

// ---------------- per-edge coefficient (CSC order): dinv[src]*p ----------------
__global__ void ecoef_k() {
    int i = blockIdx.x * blockDim.x + threadIdx.x;
    if (i >= EE) return;
    g_ec[i] = g_dinv[g_crow[i]] * g_p[g_cpidx[i]];
}

// ---------------- TF32 tensor-core GEMM: [NN,128] x [128,128] ----------------
// Block: 256 threads (8 warps), tile M=64 x N=128, whole K=128 resident in smem.
// Warp w: rows (w&3)*16, cols (w>>2)*64 (4 n-tiles of 16). NN % 16 == 0, so
// every 16-row tile is fully in-range or fully out.
__global__ __launch_bounds__(256) void gemm_tf32_k(const float* __restrict__ A,
                                                   const float* __restrict__ W,
                                                   float* __restrict__ O, int relu_in) {
    extern __shared__ float smem[];
    float* Ws = smem;             // [128][128]
    float* As = smem + 128 * 128; // [64][132]
    const int LDA = 132;
    int tid = threadIdx.x;
    int m0 = blockIdx.x * 64;

    // stage W (pre-rounded to tf32)
#pragma unroll
    for (int i = tid; i < 128 * 128 / 4; i += 256) {
        float4 v = ((const float4*)W)[i];
        v.x = wmma::__float_to_tf32(v.x);
        v.y = wmma::__float_to_tf32(v.y);
        v.z = wmma::__float_to_tf32(v.z);
        v.w = wmma::__float_to_tf32(v.w);
        ((float4*)Ws)[i] = v;
    }
    // stage A tile (64 x 128), relu + tf32 round
#pragma unroll
    for (int l = 0; l < 2; l++) {
        int idx = tid + l * 256;           // 0..511
        int r = idx >> 3, k4 = idx & 7;    // 64 rows x 8 float4... wait 128/4=32
        (void)r; (void)k4;
    }
    // (correct indexing: 64 rows x 32 float4 = 2048 float4, 8 per thread)
#pragma unroll
    for (int l = 0; l < 8; l++) {
        int idx = tid + l * 256;           // 0..2047
        int r = idx >> 5, k4 = idx & 31;   // row, float4-group
        int gm = m0 + r;
        float4 v = make_float4(0.f, 0.f, 0.f, 0.f);
        if (gm < NN) v = *(const float4*)&A[gm * 128 + k4 * 4];
        if (relu_in) {
            v.x = fmaxf(v.x, 0.f); v.y = fmaxf(v.y, 0.f);
            v.z = fmaxf(v.z, 0.f); v.w = fmaxf(v.w, 0.f);
        }
        v.x = wmma::__float_to_tf32(v.x);
        v.y = wmma::__float_to_tf32(v.y);
        v.z = wmma::__float_to_tf32(v.z);
        v.w = wmma::__float_to_tf32(v.w);
        *(float4*)&As[r * LDA + k4 * 4] = v;
    }
    __syncthreads();

    int warp = tid >> 5;
    int mi = warp & 3;          // 0..3 -> rows mi*16
    int nh = (warp >> 2) * 64;  // 0 or 64
    wmma::fragment<wmma::accumulator, 16, 16, 8, float> acc[4];
#pragma unroll
    for (int t = 0; t < 4; t++) wmma::fill_fragment(acc[t], 0.f);

#pragma unroll
    for (int k = 0; k < 128; k += 8) {
        wmma::fragment<wmma::matrix_a, 16, 16, 8, wmma::precision::tf32, wmma::row_major> af;
        wmma::load_matrix_sync(af, As + mi * 16 * LDA + k, LDA);
#pragma unroll
        for (int t = 0; t < 4; t++) {
            wmma::fragment<wmma::matrix_b, 16, 16, 8, wmma::precision::tf32, wmma::row_major> bf;
            wmma::load_matrix_sync(bf, Ws + k * 128 + nh + t * 16, 128);
            wmma::mma_sync(acc[t], af, bf, acc[t]);
        }
    }

    int gm = m0 + mi * 16;
    if (gm < NN) {
#pragma unroll
        for (int t = 0; t < 4; t++)
            wmma::store_matrix_sync(O + gm * 128 + nh + t * 16, acc[t], 128, wmma::mem_row_major);
    }
}

// ---------------- GCN aggregation: gather by destination, fused bias+self ----------------
__global__ void gather_conv_k(const float* __restrict__ h, const float* __restrict__ bias,
                              float* __restrict__ out) {
    int t = blockIdx.x * blockDim.x + threadIdx.x;
    int v = t >> 5, lane = t & 31;
    if (v >= NN) return;
    int st = g_startC[v], d = g_startC[v + 1] - st;
    float4 acc = make_float4(0.f, 0.f, 0.f, 0.f);
    for (int j0 = 0; j0 < d; j0 += 32) {
        int i = j0 + lane;
        int u = 0; float c = 0.f;
        if (i < d) { u = g_crow[st + i]; c = g_ec[st + i]; }
        int lim = min(32, d - j0);
        for (int j = 0; j < lim; j++) {
            float cj = __shfl_sync(0xffffffffu, c, j);
            int uj = __shfl_sync(0xffffffffu, u, j);
            if (cj == 0.f) continue;  // pruned edge
            float4 hv = *(const float4*)&h[uj * 128 + lane * 4];
            acc.x += cj * hv.x; acc.y += cj * hv.y;
            acc.z += cj * hv.z; acc.w += cj * hv.w;
        }
    }
    float dv = g_dinv[v];
    float4 hv = *(const float4*)&h[v * 128 + lane * 4];
    float4 bv = *(const float4*)&bias[lane * 4];
    float4 o = make_float4(bv.x + dv * (acc.x + dv * hv.x),
                           bv.y + dv * (acc.y + dv * hv.y),
                           bv.z + dv * (acc.z + dv * hv.z),
                           bv.w + dv * (acc.w + dv * hv.w));
    *(float4*)&out[v * 128 + lane * 4] = o;
}

// ---------------- pooling (batch sorted -> run-length local reduce) ----------------
__global__ void hist_batch_k(const int* __restrict__ batch) {
    int i = blockIdx.x * blockDim.x + threadIdx.x;
    if (i < NN) atomicAdd(&g_cntg[batch[i]], 1);
}

__global__ void pool_k(const float* __restrict__ z, const int* __restrict__ batch, int boff) {
    int f = threadIdx.x;  // 128 threads = one feature each
    int n0 = blockIdx.x * 256;
    if (n0 >= NN) return;
    int nend = min(n0 + 256, NN);
    int cur = batch[n0];
    float ls = 0.f, lm = 0.f;
    for (int n = n0; n < nend; n++) {
        int g = batch[n];
        if (g != cur) {
            atomicAdd(&g_feats[cur * F6 + boff + f], ls);
            atomicMax((int*)&g_feats[cur * F6 + boff + 128 + f], __float_as_int(lm));
            ls = 0.f; lm = 0.f; cur = g;
        }
        float v = fmaxf(z[n * 128 + f], 0.f);  // z = relu(conv2 out) >= 0
        ls += v;
        lm = fmaxf(lm, v);
    }
    atomicAdd(&g_feats[cur * F6 + boff + f], ls);
    atomicMax((int*)&g_feats[cur * F6 + boff + 128 + f], __float_as_int(lm));
}

__global__ void finalize_mean_k() {
    int i = blockIdx.x * blockDim.x + threadIdx.x;
    if (i >= GG * 384) return;
    int g = i / 384, r = i % 384;
    int b = r >> 7, f = r & 127;
    float c = (float)max(g_cntg[g], 1);
    g_feats[g * F6 + b * 256 + f] /= c;
}

// ---------------- tiny MLP head ----------------
__global__ void mlp1_k(const float* __restrict__ w, const float* __restrict__ bias) {
    __shared__ float sh[F6];
    int g = blockIdx.x, j = threadIdx.x;  // 256 threads
    for (int i = j; i < F6; i += 256) sh[i] = g_feats[g * F6 + i];
    __syncthreads();
    float acc = bias[j];
#pragma unroll 8
    for (int i = 0; i < F6; i++) acc += sh[i] * w[i * 256 + j];
    g_mlp1[g * 256 + j] = fmaxf(acc, 0.f);
}

__global__ void mlp2_k(const float* __restrict__ w, const float* __restrict__ bias) {
    __shared__ float sh[256];
    int g = blockIdx.x, j = threadIdx.x;  // 128 threads
    for (int i = j; i < 256; i += 128) sh[i] = g_mlp1[g * 256 + i];
    __syncthreads();
    float acc = bias[j];
#pragma unroll 8
    for (int i = 0; i < 256; i++) acc += sh[i] * w[i * 128 + j];
    g_mlp2[g * 128 + j] = fmaxf(acc, 0.f);
}

__global__ void mlp3_k(const float* __restrict__ w, const float* __restrict__ bias,
                       float* __restrict__ out) {
    int g = blockIdx.x, lane = threadIdx.x;  // 32 threads
    __shared__ float sh[128];
    for (int i = lane; i < 128; i += 32) sh[i] = g_mlp2[g * 128 + i];
    __syncwarp();
    float acc[NCLS];
#pragma unroll
    for (int c = 0; c < NCLS; c++) acc[c] = 0.f;
    for (int i = lane; i < 128; i += 32) {
        float v = sh[i];
#pragma unroll
        for (int c = 0; c < NCLS; c++) acc[c] += v * w[i * NCLS + c];
    }
#pragma unroll
    for (int c = 0; c < NCLS; c++)
#pragma unroll
        for (int o = 16; o > 0; o >>= 1) acc[c] += __shfl_xor_sync(0xffffffffu, acc[c], o);
    if (lane == 0) {
        float vals[NCLS], m = -1e30f;
        for (int c = 0; c < NCLS; c++) { vals[c] = acc[c] + bias[c]; m = fmaxf(m, vals[c]); }
        float s = 0.f;
        for (int c = 0; c < NCLS; c++) s += expf(vals[c] - m);
        float lse = logf(s);
        for (int c = 0; c < NCLS; c++) out[g * NCLS + c] = vals[c] - m - lse;
    }
}

// ---------------- host launch ----------------
extern "C" void kernel_launch(void* const* d_in, const int* in_sizes, int n_in,
                              void* d_out, int out_size) {
    const float* x = (const float*)d_in[0];
    const int* ei = (const int*)d_in[1];
    // d_in[2] = edge_attr: unused by the reference
    const int* batch = (const int*)d_in[3];
    int pi = (n_in >= 16) ? 5 : 4;
    const float* att  = (const float*)d_in[pi + 0];
    const float* W1   = (const float*)d_in[pi + 1];
    const float* b1   = (const float*)d_in[pi + 2];
    const float* W2   = (const float*)d_in[pi + 3];
    const float* b2   = (const float*)d_in[pi + 4];
    const float* fc1w = (const float*)d_in[pi + 5];
    const float* fc1b = (const float*)d_in[pi + 6];
    const float* fc2w = (const float*)d_in[pi + 7];
    const float* fc2b = (const float*)d_in[pi + 8];
    const float* fc3w = (const float*)d_in[pi + 9];
    const float* fc3b = (const float*)d_in[pi + 10];
    float* out = (float*)d_out;

    float *bufA, *bufB, *feats;
    int *cntR, *cntC, *startR, *startC, *curR, *curC;
    int *inclR, *inclC, *bsumR, *bsumC;
    cudaGetSymbolAddress((void**)&bufA, g_bufA);
    cudaGetSymbolAddress((void**)&bufB, g_bufB);
    cudaGetSymbolAddress((void**)&feats, g_feats);
    cudaGetSymbolAddress((void**)&cntR, g_cntR);
    cudaGetSymbolAddress((void**)&cntC, g_cntC);
    cudaGetSymbolAddress((void**)&startR, g_startR);
    cudaGetSymbolAddress((void**)&startC, g_startC);
    cudaGetSymbolAddress((void**)&curR, g_curR);
    cudaGetSymbolAddress((void**)&curC, g_curC);
    cudaGetSymbolAddress((void**)&inclR, g_inclR);
    cudaGetSymbolAddress((void**)&inclC, g_inclC);
    cudaGetSymbolAddress((void**)&bsumR, g_bsumR);
    cudaGetSymbolAddress((void**)&bsumC, g_bsumC);

    cudaFuncSetAttribute(gemm_tf32_k, cudaFuncAttributeMaxDynamicSharedMemorySize,
                         GEMM_SMEM_BYTES);

    const int* row = ei;
    const int* col = ei + EE;

    // CSR (by source) + CSC (by dest), built once, reused by all 3 blocks
    zero_i2<<<cdiv(NN, 256), 256>>>(cntR, cntC, NN);
    hist_e<<<cdiv(EE, 256), 256>>>(row, col);
    scan_local<<<NB, 1024>>>(cntR, inclR, bsumR, cntC, inclC, bsumC);
    scan_bsum2<<<1, 128>>>(bsumR);
    scan_bsum2<<<1, 128>>>(bsumC);
    scan_final<<<NB, 1024>>>(cntR, inclR, bsumR, startR, curR,
                             cntC, inclC, bsumC, startC, curC);
    scatter_e<<<cdiv(EE, 256), 256>>>(row, col);

    // attention scores for all blocks
    s12_k<<<cdiv(NN * 32, 256), 256>>>(x, att);

    // per-graph node counts + clear pooled features
    zero_cntg_k<<<1, 256>>>();
    hist_batch_k<<<cdiv(NN, 256), 256>>>(batch);
    zero_f<<<cdiv(GG * F6, 256), 256>>>(feats, GG * F6);

    for (int b = 0; b < 3; b++) {
        sparsemax_k<<<cdiv(NN, 8), 256>>>(b);
        dinv_k<<<cdiv(NN * 32, 256), 256>>>();
        ecoef_k<<<cdiv(EE, 256), 256>>>();

        // conv1: h = x @ W1; out = b1 + dinv*(gather + dinv*h)
        gemm_tf32_k<<<cdiv(NN, 64), 256, GEMM_SMEM_BYTES>>>(x, W1 + b * 128 * 128, bufA, 0);
        gather_conv_k<<<cdiv(NN * 32, 256), 256>>>(bufA, b1 + b * 128, bufB);

        // conv2: h = relu(conv1) @ W2 (relu fused into GEMM load)
        gemm_tf32_k<<<cdiv(NN, 64), 256, GEMM_SMEM_BYTES>>>(bufB, W2 + b * 128 * 128, bufA, 1);
        gather_conv_k<<<cdiv(NN * 32, 256), 256>>>(bufA, b2 + b * 128, bufB);

        // pool relu(conv2) into feats[g][b*256 .. b*256+255]
        pool_k<<<cdiv(NN, 256), 128>>>(bufB, batch, b * 256);
    }

    finalize_mean_k<<<cdiv(GG * 384, 256), 256>>>();
    mlp1_k<<<GG, 256>>>(fc1w, fc1b);
    mlp2_k<<<GG, 128>>>(fc2w, fc2b);
    mlp3_k<<<GG, 32>>>(fc3w, fc3b, out);

    (void)in_sizes;
    (void)out_size;
}